// round 17
// baseline (speedup 1.0000x reference)
#include <cuda_runtime.h>
#include <cuda_fp16.h>
#include <cstdint>

// ---------------- problem constants ----------------
namespace {
constexpr int kE = 512, kF = 2048, kQ = 8;
constexpr int kRows = 16384;

// GEMM tiling: 2 CTAs/SM, A via pre-fragmented LDG, B via smem
constexpr int BM = 128, BN = 128, BK = 64, STAGES = 3;
constexpr int GTHR = 256;                    // 8 warps: 2 (m) x 4 (n), warp tile 64x32
constexpr int STAGE_BYTES = BN * 128;        // B only: 16KB
constexpr int GSMEM = STAGES * STAGE_BYTES;  // 48KB
constexpr int NCHUNK = kF / BK;              // 32

// act kernel: 128 rows/CTA, fragment-order output
constexpr int ATHR = 256;
constexpr int ABM  = 128;
constexpr int ASM_W1  = 0;                   // f32 [8][2048] = 64KB
constexpr int ASM_B1  = 65536;               // f32 [2048] = 8KB
constexpr int ASM_Z   = 73728;               // f32 [128][8] = 4KB
constexpr int ASM_STG = 77824;               // 2 x 16KB stage
constexpr int ASMEM   = 110592;              // 108KB -> 2 CTAs/SM
}

__device__ __align__(16) __half g_w2h[kE * kF];  // fp16 w2
// A in fragment order: [blk(128)][chunk(32)][mfrag(8)][kc(4)][lane(32)] x 16B (+1 chunk pad)
__device__ __align__(16) uint4 g_actp[((size_t)128 * 32 + 1) * 8 * 4 * 32];

// ---------------- helpers ----------------
__device__ __forceinline__ uint32_t smem_u32(const void* p) {
    uint32_t a;
    asm("{ .reg .u64 t; cvta.to.shared.u64 t, %1; cvt.u32.u64 %0, t; }" : "=r"(a) : "l"(p));
    return a;
}
__device__ __forceinline__ uint32_t sw128(uint32_t off) { return off ^ ((off >> 3) & 0x70); }

__device__ __forceinline__ void cp_async16(uint32_t dst, const void* src) {
    asm volatile("cp.async.cg.shared.global [%0], [%1], 16;" :: "r"(dst), "l"(src) : "memory");
}
__device__ __forceinline__ void cp_commit() {
    asm volatile("cp.async.commit_group;" ::: "memory");
}
__device__ __forceinline__ void cp_wait1() {
    asm volatile("cp.async.wait_group 1;" ::: "memory");
}

__device__ __forceinline__ void ldsm4(uint32_t* r, uint32_t addr) {
    asm volatile("ldmatrix.sync.aligned.m8n8.x4.shared.b16 {%0,%1,%2,%3}, [%4];"
        : "=r"(r[0]), "=r"(r[1]), "=r"(r[2]), "=r"(r[3]) : "r"(addr));
}
__device__ __forceinline__ void mma16816(float* d, const uint32_t* a, const uint32_t* b) {
    asm volatile(
        "mma.sync.aligned.m16n8k16.row.col.f32.f16.f16.f32 "
        "{%0,%1,%2,%3}, {%4,%5,%6,%7}, {%8,%9}, {%0,%1,%2,%3};"
        : "+f"(d[0]), "+f"(d[1]), "+f"(d[2]), "+f"(d[3])
        : "r"(a[0]), "r"(a[1]), "r"(a[2]), "r"(a[3]), "r"(b[0]), "r"(b[1]));
}

// ---------------- kernel 1: w2 -> fp16 ----------------
__global__ void ffq_convert_w2(const float* __restrict__ w2) {
    int i = blockIdx.x * blockDim.x + threadIdx.x;
    float4 v = __ldg(reinterpret_cast<const float4*>(w2) + i);
    __half2* dst = reinterpret_cast<__half2*>(g_w2h);
    dst[2 * i]     = __floats2half2_rn(v.x, v.y);
    dst[2 * i + 1] = __floats2half2_rn(v.z, v.w);
}

// ---------------- kernel 2: fused act -> fragment-order A ----------------
__global__ void __launch_bounds__(ATHR, 2)
ffq_act(const float* __restrict__ x, const float* __restrict__ ry,
        const float* __restrict__ w1, const float* __restrict__ b1) {
    extern __shared__ char smem[];
    const uint32_t sb = smem_u32(smem);
    float* w1t = reinterpret_cast<float*>(smem + ASM_W1);  // [q][f]
    float* b1s = reinterpret_cast<float*>(smem + ASM_B1);
    float* zs  = reinterpret_cast<float*>(smem + ASM_Z);   // [row][q]
    const int tid = threadIdx.x;

    {   // stage w1 transposed: thread covers f = tid*8 .. +7
        const int f = tid * 8;
#pragma unroll
        for (int j = 0; j < 8; j++) {
            const float4* p = reinterpret_cast<const float4*>(w1 + (size_t)(f + j) * kQ);
            float4 a = __ldg(p), b = __ldg(p + 1);
            w1t[0 * kF + f + j] = a.x; w1t[1 * kF + f + j] = a.y;
            w1t[2 * kF + f + j] = a.z; w1t[3 * kF + f + j] = a.w;
            w1t[4 * kF + f + j] = b.x; w1t[5 * kF + f + j] = b.y;
            w1t[6 * kF + f + j] = b.z; w1t[7 * kF + f + j] = b.w;
        }
        *reinterpret_cast<float4*>(b1s + f)     = __ldg(reinterpret_cast<const float4*>(b1 + f));
        *reinterpret_cast<float4*>(b1s + f + 4) = __ldg(reinterpret_cast<const float4*>(b1 + f + 4));
    }
    if (tid < ABM) {  // z[row][q]
        const float4* xp =
            reinterpret_cast<const float4*>(x + (size_t)(blockIdx.x * ABM + tid) * kE);
        float4 a = __ldg(xp), b = __ldg(xp + 1);
        float xs[8] = {a.x, a.y, a.z, a.w, b.x, b.y, b.z, b.w};
#pragma unroll
        for (int q = 0; q < 8; q++) zs[tid * 8 + q] = cosf(xs[q]) * cosf(__ldg(ry + q));
    }
    __syncthreads();

    // phase1 role: rows rg*8..+7, cols cg*4..+3 (within 64-col chunk)
    const int rg = tid >> 4;          // 0..15
    const int cg = tid & 15;          // 0..15
    float zr[8][8];
#pragma unroll
    for (int rr = 0; rr < 8; rr++) {
        const float4* zp = reinterpret_cast<const float4*>(zs + (rg * 8 + rr) * 8);
        float4 z0 = zp[0], z1 = zp[1];
        zr[rr][0] = z0.x; zr[rr][1] = z0.y; zr[rr][2] = z0.z; zr[rr][3] = z0.w;
        zr[rr][4] = z1.x; zr[rr][5] = z1.y; zr[rr][6] = z1.z; zr[rr][7] = z1.w;
    }

    // phase2 role: warp w -> mfrag w (rows w*16..+15)
    const int w = tid >> 5, lane = tid & 31;
    const uint32_t xm   = (uint32_t)((lane & 7) << 4);
    const uint32_t prow = (uint32_t)(w * 16 + (lane & 15)) * 128;
    const uint32_t pc0  = (uint32_t)((lane >> 4) * 16);
    uint4* outp = g_actp + ((size_t)blockIdx.x * NCHUNK) * (8 * 4 * 32);

#pragma unroll 1
    for (int c = 0; c < NCHUNK; c++) {
        char* stg = smem + ASM_STG + (c & 1) * 16384;
        // ---- phase1: compute h for rows rg*8..+7, cols c*64+cg*4..+3 ----
        {
            const int f0 = c * BK + cg * 4;
            float4 wq[8];
#pragma unroll
            for (int q = 0; q < 8; q++)
                wq[q] = *reinterpret_cast<const float4*>(w1t + q * kF + f0);
            const float4 bq = *reinterpret_cast<const float4*>(b1s + f0);
#pragma unroll
            for (int rr = 0; rr < 8; rr++) {
                float h0 = bq.x, h1 = bq.y, h2 = bq.z, h3 = bq.w;
#pragma unroll
                for (int q = 0; q < 8; q++) {
                    const float z = zr[rr][q];
                    h0 = fmaf(z, wq[q].x, h0); h1 = fmaf(z, wq[q].y, h1);
                    h2 = fmaf(z, wq[q].z, h2); h3 = fmaf(z, wq[q].w, h3);
                }
                __half2 p0 = __floats2half2_rn(fmaxf(h0, 0.f), fmaxf(h1, 0.f));
                __half2 p1 = __floats2half2_rn(fmaxf(h2, 0.f), fmaxf(h3, 0.f));
                uint2 pk;
                pk.x = *reinterpret_cast<uint32_t*>(&p0);
                pk.y = *reinterpret_cast<uint32_t*>(&p1);
                const uint32_t off = (uint32_t)((rg * 8 + rr) * 128 + cg * 8);
                *reinterpret_cast<uint2*>(stg + sw128(off)) = pk;
            }
        }
        __syncthreads();
        // ---- phase2: ldsm fragment read + STG in frag order ----
        {
            const uint32_t sgb = sb + ASM_STG + (uint32_t)((c & 1) * 16384);
            uint4* op = outp + ((size_t)c * 8 + w) * (4 * 32) + lane;
#pragma unroll
            for (int kc = 0; kc < 4; kc++) {
                uint32_t r[4];
                ldsm4(r, sgb + prow + ((pc0 + (uint32_t)(kc * 32)) ^ xm));
                op[kc * 32] = make_uint4(r[0], r[1], r[2], r[3]);
            }
        }
    }
}

// ---------------- kernel 3: GEMM out = act @ w2^T + b2, 2 CTAs/SM ----------------
__global__ void __launch_bounds__(GTHR, 2)
ffq_gemm(const float* __restrict__ b2, float* __restrict__ out) {
    extern __shared__ char smem[];
    const uint32_t sb = smem_u32(smem);
    const int tid  = threadIdx.x;
    const int lane = tid & 31;
    const int wid  = tid >> 5;
    const int wm   = wid >> 2;            // 0..1 (m)
    const int wn   = wid & 3;             // 0..3 (n)
    const int blkm = blockIdx.x >> 2;
    const int n0   = (blockIdx.x & 3) * BN;
    const int m0   = blkm * BM;

    // B fill: per thread 4 x 16B segs
    const int fr = tid >> 3, fj = tid & 7;
    const uint32_t boff = sw128((uint32_t)(fr * 128 + fj * 16));
    const __half* bsrc0 = g_w2h + (size_t)(n0 + fr) * kF + fj * 8;

    auto fill_B = [&](int st, int c) {
        const uint32_t Bs = sb + st * STAGE_BYTES;
#pragma unroll
        for (int i = 0; i < 4; i++)
            cp_async16(Bs + boff + (uint32_t)(i * 4096), bsrc0 + (size_t)(i * 32) * kF + c * BK);
    };

    fill_B(0, 0); cp_commit();
    fill_B(1, 1); cp_commit();

    float acc[4][4][4];
#pragma unroll
    for (int mi = 0; mi < 4; mi++)
#pragma unroll
        for (int ni = 0; ni < 4; ni++)
#pragma unroll
            for (int j = 0; j < 4; j++) acc[mi][ni][j] = 0.f;

    const uint32_t xm     = (uint32_t)((lane & 7) << 4);
    const uint32_t b_rowb = (uint32_t)(wn * 32 + ((lane >> 4) & 1) * 8 + (lane & 7)) * 128;
    const uint32_t b_c0   = (uint32_t)(((lane >> 3) & 1) * 16);

    uint32_t af[2][4][4], bf[2][2][4];

    // preload chunk0 kc0 A frags (pure LDG; independent of cp.async stages)
    {
        const uint4* ap = g_actp + ((size_t)(blkm * NCHUNK) * 8 + wm * 4) * 128 + lane;
#pragma unroll
        for (int mi = 0; mi < 4; mi++) {
            uint4 v = __ldg(ap + mi * 128);
            af[0][mi][0] = v.x; af[0][mi][1] = v.y; af[0][mi][2] = v.z; af[0][mi][3] = v.w;
        }
    }

    auto chunk_iter = [&](int c, int st, int pst) __attribute__((always_inline)) {
        cp_wait1();
        __syncthreads();
        if (c + 2 < NCHUNK) fill_B(pst, c + 2);
        cp_commit();

        const uint32_t Bb = sb + st * STAGE_BYTES;
        const uint4* ap = g_actp + (((size_t)(blkm * NCHUNK + c)) * 8 + wm * 4) * 128 + lane;

#pragma unroll
        for (int np = 0; np < 2; np++)
            ldsm4(bf[0][np], Bb + b_rowb + (uint32_t)(np * 2048) + (b_c0 ^ xm));

#pragma unroll
        for (int kc = 0; kc < 4; kc++) {
            const int cur = kc & 1, nxt = cur ^ 1;
            if (kc < 3) {
                // prefetch next kc: A via LDG, B via ldsm
#pragma unroll
                for (int mi = 0; mi < 4; mi++) {
                    uint4 v = __ldg(ap + mi * 128 + (kc + 1) * 32);
                    af[nxt][mi][0] = v.x; af[nxt][mi][1] = v.y;
                    af[nxt][mi][2] = v.z; af[nxt][mi][3] = v.w;
                }
                const uint32_t bc = ((b_c0 + (uint32_t)((kc + 1) * 32)) ^ xm);
#pragma unroll
                for (int np = 0; np < 2; np++)
                    ldsm4(bf[nxt][np], Bb + b_rowb + (uint32_t)(np * 2048) + bc);
            } else {
                // kc==3: prefetch NEXT chunk's kc0 A frags (pad covers last chunk)
                const uint4* apn = ap + 8 * 128;
#pragma unroll
                for (int mi = 0; mi < 4; mi++) {
                    uint4 v = __ldg(apn + mi * 128);
                    af[nxt][mi][0] = v.x; af[nxt][mi][1] = v.y;
                    af[nxt][mi][2] = v.z; af[nxt][mi][3] = v.w;
                }
            }
#pragma unroll
            for (int mi = 0; mi < 4; mi++)
#pragma unroll
                for (int ni = 0; ni < 4; ni++) {
                    uint32_t bb[2] = {bf[cur][ni >> 1][(ni & 1) * 2],
                                      bf[cur][ni >> 1][(ni & 1) * 2 + 1]};
                    mma16816(acc[mi][ni], af[cur][mi], bb);
                }
        }
    };

    // stage-residue unrolled chunk loop: st = c%3 as literals
#pragma unroll 1
    for (int cb = 0; cb < NCHUNK; cb += 3) {
        chunk_iter(cb, 0, 2);
        if (cb + 1 < NCHUNK) chunk_iter(cb + 1, 1, 0);
        if (cb + 2 < NCHUNK) chunk_iter(cb + 2, 2, 1);
    }

    // epilogue
#pragma unroll
    for (int ni = 0; ni < 4; ni++) {
        const int colp = n0 + wn * 32 + ni * 8 + (lane & 3) * 2;
        const float2 bv = __ldg(reinterpret_cast<const float2*>(b2 + colp));
#pragma unroll
        for (int mi = 0; mi < 4; mi++) {
            const int row0 = m0 + wm * 64 + mi * 16 + (lane >> 2);
            float2 v0 = make_float2(acc[mi][ni][0] + bv.x, acc[mi][ni][1] + bv.y);
            float2 v1 = make_float2(acc[mi][ni][2] + bv.x, acc[mi][ni][3] + bv.y);
            *reinterpret_cast<float2*>(out + (size_t)row0 * kE + colp) = v0;
            *reinterpret_cast<float2*>(out + (size_t)(row0 + 8) * kE + colp) = v1;
        }
    }
}

// ---------------- launch ----------------
extern "C" void kernel_launch(void* const* d_in, const int* in_sizes, int n_in,
                              void* d_out, int out_size) {
    (void)in_sizes; (void)n_in; (void)out_size;
    const float* x  = (const float*)d_in[0];
    const float* ry = (const float*)d_in[1];
    const float* w1 = (const float*)d_in[2];
    const float* b1 = (const float*)d_in[3];
    const float* w2 = (const float*)d_in[4];
    const float* b2 = (const float*)d_in[5];
    float* out = (float*)d_out;

    ffq_convert_w2<<<1024, 256>>>(w2);

    cudaFuncSetAttribute(ffq_act, cudaFuncAttributeMaxDynamicSharedMemorySize, ASMEM);
    ffq_act<<<kRows / ABM, ATHR, ASMEM>>>(x, ry, w1, b1);

    cudaFuncSetAttribute(ffq_gemm, cudaFuncAttributeMaxDynamicSharedMemorySize, GSMEM);
    ffq_gemm<<<(kRows / BM) * (kE / BN), GTHR, GSMEM>>>(b2, out);
}